// round 11
// baseline (speedup 1.0000x reference)
#include <cuda_runtime.h>

// Problem shape (fixed by the reference)
#define BB 64
#define SS 2048
#define DD 256
#define NSPLIT 16
#define NI (SS / NSPLIT)             // 128 strided row-indices per CTA
#define BATCH 8                      // in-flight float4 loads per thread
#define NSUB (NI / (4 * BATCH))      // 4 sub-batches of 32 indices

// Global scratch (statically zero-initialized; reset by the finalizing CTA each
// call so graph replays see a clean state).
__device__ float    g_sum [BB * DD];
__device__ unsigned g_maxo[BB * DD];   // order-preserving uint encoding
__device__ float    g_cnt [BB];
__device__ int      g_arrived[BB];

__device__ __forceinline__ float neg_inf() { return __int_as_float(0xff800000); }

__device__ __forceinline__ unsigned f2o(float f) {
    unsigned u = __float_as_uint(f);
    return (u & 0x80000000u) ? ~u : (u | 0x80000000u);
}
__device__ __forceinline__ float o2f(unsigned u) {
    return __uint_as_float((u & 0x80000000u) ? (u & 0x7fffffffu) : ~u);
}
__device__ __forceinline__ int arrive_acq_rel(int* addr) {
    int old;
    asm volatile("atom.add.acq_rel.gpu.global.s32 %0, [%1], 1;"
                 : "=r"(old) : "l"(addr) : "memory");
    return old;
}

// One CTA per (split, b). Rows are assigned STRIDED: s = split + 16*i,
// i = 0..127, so for a prefix mask every CTA of batch b gets ~L_b/16 valid
// rows — per-SM work is intrinsically balanced. Validity in i-space is still a
// prefix, so the warp-uniform 32-index sub-batch skip and the select-free
// all-valid fast path are preserved.
// 256 threads: d4 = tid % 64 (float4 lane over D=256), sg = tid / 64
// (4 strided indices in parallel; mask addresses warp-uniform).
__global__ void __launch_bounds__(256, 4)
pool_strided(const float* __restrict__ feats,
             const float* __restrict__ mask,
             float* __restrict__ out) {
    const int split = blockIdx.x;
    const int b     = blockIdx.y;
    const int tid   = threadIdx.x;
    const int d4    = tid & 63;
    const int sg    = tid >> 6;

    // Thread's first row: i = sg  ->  s = split + 16*sg; i-stride 4 -> s-stride 64.
    const float4* __restrict__ p =
        reinterpret_cast<const float4*>(feats) +
        ((size_t)b * SS + split + 16 * sg) * 64 + d4;
    const float* __restrict__ mp = mask + (size_t)b * SS + split + 16 * sg;

    float4 sum = make_float4(0.f, 0.f, 0.f, 0.f);
    float4 mx  = make_float4(neg_inf(), neg_inf(), neg_inf(), neg_inf());
    float  cnt = 0.f;

    // Prime the mask pipeline with sub-batch 0 (i-stride 4 => s-stride 64)
    float mbuf[BATCH];
#pragma unroll
    for (int j = 0; j < BATCH; ++j) mbuf[j] = __ldca(mp + j * 64);

#pragma unroll
    for (int k = 0; k < NSUB; ++k) {
        bool allv = true, anyv = false;
#pragma unroll
        for (int j = 0; j < BATCH; ++j) {
            const bool v = (mbuf[j] > 0.f);
            allv &= v;
            anyv |= v;
        }

        // Prefetch next sub-batch's masks before touching feats
        float mnext[BATCH];
        if (k + 1 < NSUB) {
#pragma unroll
            for (int j = 0; j < BATCH; ++j)
                mnext[j] = __ldca(mp + (k + 1) * 32 * 16 + j * 64);
        }

        // Sub-batch k: i = 32k + 4j + sg  ->  row offset 16*(32k+4j) from base
        const float4* __restrict__ pk = p + (size_t)k * 32 * 16 * 64;
        if (allv) {
            float4 fbuf[BATCH];
#pragma unroll
            for (int j = 0; j < BATCH; ++j) fbuf[j] = __ldcs(pk + (size_t)j * 64 * 64);
#pragma unroll
            for (int j = 0; j < BATCH; ++j) {
                const float  m = mbuf[j];
                const float4 f = fbuf[j];
                cnt += m;
                sum.x += f.x * m;  sum.y += f.y * m;
                sum.z += f.z * m;  sum.w += f.w * m;
                mx.x = fmaxf(mx.x, f.x);
                mx.y = fmaxf(mx.y, f.y);
                mx.z = fmaxf(mx.z, f.z);
                mx.w = fmaxf(mx.w, f.w);
            }
        } else if (anyv) {
            float4 fbuf[BATCH];
#pragma unroll
            for (int j = 0; j < BATCH; ++j) fbuf[j] = __ldcs(pk + (size_t)j * 64 * 64);
#pragma unroll
            for (int j = 0; j < BATCH; ++j) {
                const float  m = mbuf[j];
                const float4 f = fbuf[j];
                const bool   v = (m > 0.f);
                cnt += m;
                sum.x += f.x * m;  sum.y += f.y * m;
                sum.z += f.z * m;  sum.w += f.w * m;
                mx.x = fmaxf(mx.x, v ? f.x : neg_inf());
                mx.y = fmaxf(mx.y, v ? f.y : neg_inf());
                mx.z = fmaxf(mx.z, v ? f.z : neg_inf());
                mx.w = fmaxf(mx.w, v ? f.w : neg_inf());
            }
        }
        // else: fully-masked sub-batch — skip feats loads entirely.

#pragma unroll
        for (int j = 0; j < BATCH; ++j) mbuf[j] = mnext[j];
    }

    // CTA-level reduce: 4 sg-groups -> 1 (64 float4 lanes remain)
    __shared__ float4 s_sum[256];
    __shared__ float4 s_max[256];
    __shared__ float  s_cnt[4];
    s_sum[tid] = sum;
    s_max[tid] = mx;
    if (d4 == 0) s_cnt[sg] = cnt;
    __syncthreads();

    if (tid < 64) {
        const float ctot = s_cnt[0] + s_cnt[1] + s_cnt[2] + s_cnt[3];
        if (ctot > 0.f) {   // dead CTAs contribute identities — skip the flush
            float4 a = s_sum[tid];
            float4 m = s_max[tid];
#pragma unroll
            for (int k = 1; k < 4; ++k) {
                float4 a2 = s_sum[tid + 64 * k];
                float4 m2 = s_max[tid + 64 * k];
                a.x += a2.x; a.y += a2.y; a.z += a2.z; a.w += a2.w;
                m.x = fmaxf(m.x, m2.x); m.y = fmaxf(m.y, m2.y);
                m.z = fmaxf(m.z, m2.z); m.w = fmaxf(m.w, m2.w);
            }
            const int dbase = b * DD + tid * 4;
            atomicAdd(&g_sum[dbase + 0], a.x);
            atomicAdd(&g_sum[dbase + 1], a.y);
            atomicAdd(&g_sum[dbase + 2], a.z);
            atomicAdd(&g_sum[dbase + 3], a.w);
            atomicMax(&g_maxo[dbase + 0], f2o(m.x));
            atomicMax(&g_maxo[dbase + 1], f2o(m.y));
            atomicMax(&g_maxo[dbase + 2], f2o(m.z));
            atomicMax(&g_maxo[dbase + 3], f2o(m.w));
            if (tid == 0) atomicAdd(&g_cnt[b], ctot);
        }
    }

    // Arrival: syncthreads orders every thread's flushes before tid0's acq_rel add.
    __syncthreads();
    __shared__ int s_last;
    if (tid == 0)
        s_last = (arrive_acq_rel(&g_arrived[b]) == NSPLIT - 1);
    __syncthreads();
    if (!s_last) return;

    // Last CTA for this b: accumulators final (acquire above). Write output,
    // reset scratch for the next graph replay.
    {
        const int d = tid;  // 0..255
        float    fsum = __ldcg(&g_sum[b * DD + d]);
        unsigned mo   = __ldcg(&g_maxo[b * DD + d]);
        float    fcnt = __ldcg(&g_cnt[b]);
        out[(size_t)b * (2 * DD) + d]      = o2f(mo);
        out[(size_t)b * (2 * DD) + DD + d] = fsum / fcnt;
        __stcg(&g_sum[b * DD + d], 0.f);
        __stcg(&g_maxo[b * DD + d], 0u);
        if (tid == 0) {
            __stcg(&g_cnt[b], 0.f);
            __stcg(&g_arrived[b], 0);
        }
    }
}

extern "C" void kernel_launch(void* const* d_in, const int* in_sizes, int n_in,
                              void* d_out, int out_size) {
    const float* feats = (const float*)d_in[0];
    const float* mask  = (const float*)d_in[1];
    float* out = (float*)d_out;

    dim3 grid(NSPLIT, BB);
    pool_strided<<<grid, 256>>>(feats, mask, out);
}

// round 12
// speedup vs baseline: 1.1577x; 1.1577x over previous
#include <cuda_runtime.h>

// Problem shape (fixed by the reference)
#define BB 64
#define SS 2048
#define DD 256
#define NSPLIT 16
#define NI (SS / NSPLIT)             // 128 strided row-indices per CTA
#define BATCH 8                      // in-flight float4 loads per thread
#define NSUB (NI / (4 * BATCH))      // 4 sub-batches of 32 indices

// Global scratch (statically zero-initialized; reset by the finalizing CTA each
// call so graph replays see a clean state).
__device__ float    g_sum [BB * DD];
__device__ unsigned g_maxo[BB * DD];   // order-preserving uint encoding
__device__ float    g_cnt [BB];
__device__ int      g_arrived[BB];

__device__ __forceinline__ float neg_inf() { return __int_as_float(0xff800000); }

__device__ __forceinline__ unsigned f2o(float f) {
    unsigned u = __float_as_uint(f);
    return (u & 0x80000000u) ? ~u : (u | 0x80000000u);
}
__device__ __forceinline__ float o2f(unsigned u) {
    return __uint_as_float((u & 0x80000000u) ? (u & 0x7fffffffu) : ~u);
}
__device__ __forceinline__ int arrive_acq_rel(int* addr) {
    int old;
    asm volatile("atom.add.acq_rel.gpu.global.s32 %0, [%1], 1;"
                 : "=r"(old) : "l"(addr) : "memory");
    return old;
}

// One CTA per (split, b). Rows assigned STRIDED: s = split + 16*i, i = 0..127,
// so for a prefix mask all 16 CTAs of batch b carry ~L_b/16 valid rows each —
// intrinsic load balance across SMs. Validity in i-space is still a prefix.
// Boundary sub-batches predicate each row's feats load on its (warp-uniform)
// mask, so ZERO wasted feats traffic. 256 threads: d4 = tid % 64 (float4 lane
// over D=256), sg = tid / 64 (4 strided indices in parallel).
__global__ void __launch_bounds__(256, 4)
pool_strided(const float* __restrict__ feats,
             const float* __restrict__ mask,
             float* __restrict__ out) {
    const int split = blockIdx.x;
    const int b     = blockIdx.y;
    const int tid   = threadIdx.x;
    const int d4    = tid & 63;
    const int sg    = tid >> 6;

    // Thread's first row: i = sg -> s = split + 16*sg; i-stride 4 -> s-stride 64.
    const float4* __restrict__ p =
        reinterpret_cast<const float4*>(feats) +
        ((size_t)b * SS + split + 16 * sg) * 64 + d4;
    const float* __restrict__ mp = mask + (size_t)b * SS + split + 16 * sg;

    float4 sum = make_float4(0.f, 0.f, 0.f, 0.f);
    float4 mx  = make_float4(neg_inf(), neg_inf(), neg_inf(), neg_inf());
    float  cnt = 0.f;

    // Prime the mask pipeline with sub-batch 0 (i-stride 4 => s-stride 64)
    float mbuf[BATCH];
#pragma unroll
    for (int j = 0; j < BATCH; ++j) mbuf[j] = __ldca(mp + j * 64);

    bool done = false;   // prefix property: after an all-invalid sub-batch, all later ones are too
#pragma unroll
    for (int k = 0; k < NSUB; ++k) {
        if (done) break;

        bool allv = true, anyv = false;
#pragma unroll
        for (int j = 0; j < BATCH; ++j) {
            const bool v = (mbuf[j] > 0.f);
            allv &= v;
            anyv |= v;
        }

        // Prefetch next sub-batch's masks before touching feats
        float mnext[BATCH];
        if (k + 1 < NSUB) {
#pragma unroll
            for (int j = 0; j < BATCH; ++j)
                mnext[j] = __ldca(mp + (k + 1) * 32 * 16 + j * 64);
        }

        // Sub-batch k: i = 32k + 4j + sg -> row offset 16*(32k+4j) from base
        const float4* __restrict__ pk = p + (size_t)k * 32 * 16 * 64;
        if (allv) {
            // All rows valid: unconditional batched loads, select-free max.
            float4 fbuf[BATCH];
#pragma unroll
            for (int j = 0; j < BATCH; ++j) fbuf[j] = __ldcs(pk + (size_t)j * 64 * 64);
#pragma unroll
            for (int j = 0; j < BATCH; ++j) {
                const float  m = mbuf[j];
                const float4 f = fbuf[j];
                cnt += m;
                sum.x += f.x * m;  sum.y += f.y * m;
                sum.z += f.z * m;  sum.w += f.w * m;
                mx.x = fmaxf(mx.x, f.x);
                mx.y = fmaxf(mx.y, f.y);
                mx.z = fmaxf(mx.z, f.z);
                mx.w = fmaxf(mx.w, f.w);
            }
        } else if (anyv) {
            // Boundary: per-row predicated loads (warp-uniform mask) — zero
            // wasted feats traffic; valid rows still need no select.
#pragma unroll
            for (int j = 0; j < BATCH; ++j) {
                const float m = mbuf[j];
                if (m > 0.f) {
                    const float4 f = __ldcs(pk + (size_t)j * 64 * 64);
                    cnt += m;
                    sum.x += f.x * m;  sum.y += f.y * m;
                    sum.z += f.z * m;  sum.w += f.w * m;
                    mx.x = fmaxf(mx.x, f.x);
                    mx.y = fmaxf(mx.y, f.y);
                    mx.z = fmaxf(mx.z, f.z);
                    mx.w = fmaxf(mx.w, f.w);
                }
            }
            done = true;   // prefix ended inside this sub-batch
        } else {
            done = true;   // fully past the prefix
        }

#pragma unroll
        for (int j = 0; j < BATCH; ++j) mbuf[j] = mnext[j];
    }

    // CTA-level reduce: 4 sg-groups -> 1 (64 float4 lanes remain)
    __shared__ float4 s_sum[256];
    __shared__ float4 s_max[256];
    __shared__ float  s_cnt[4];
    s_sum[tid] = sum;
    s_max[tid] = mx;
    if (d4 == 0) s_cnt[sg] = cnt;
    __syncthreads();

    if (tid < 64) {
        const float ctot = s_cnt[0] + s_cnt[1] + s_cnt[2] + s_cnt[3];
        if (ctot > 0.f) {   // dead CTAs contribute identities — skip the flush
            float4 a = s_sum[tid];
            float4 m = s_max[tid];
#pragma unroll
            for (int k = 1; k < 4; ++k) {
                float4 a2 = s_sum[tid + 64 * k];
                float4 m2 = s_max[tid + 64 * k];
                a.x += a2.x; a.y += a2.y; a.z += a2.z; a.w += a2.w;
                m.x = fmaxf(m.x, m2.x); m.y = fmaxf(m.y, m2.y);
                m.z = fmaxf(m.z, m2.z); m.w = fmaxf(m.w, m2.w);
            }
            const int dbase = b * DD + tid * 4;
            atomicAdd(&g_sum[dbase + 0], a.x);
            atomicAdd(&g_sum[dbase + 1], a.y);
            atomicAdd(&g_sum[dbase + 2], a.z);
            atomicAdd(&g_sum[dbase + 3], a.w);
            atomicMax(&g_maxo[dbase + 0], f2o(m.x));
            atomicMax(&g_maxo[dbase + 1], f2o(m.y));
            atomicMax(&g_maxo[dbase + 2], f2o(m.z));
            atomicMax(&g_maxo[dbase + 3], f2o(m.w));
            if (tid == 0) atomicAdd(&g_cnt[b], ctot);
        }
    }

    // Arrival: syncthreads orders every thread's flushes before tid0's acq_rel add.
    __syncthreads();
    __shared__ int s_last;
    if (tid == 0)
        s_last = (arrive_acq_rel(&g_arrived[b]) == NSPLIT - 1);
    __syncthreads();
    if (!s_last) return;

    // Last CTA for this b: accumulators final (acquire above). Write output,
    // reset scratch for the next graph replay.
    {
        const int d = tid;  // 0..255
        float    fsum = __ldcg(&g_sum[b * DD + d]);
        unsigned mo   = __ldcg(&g_maxo[b * DD + d]);
        float    fcnt = __ldcg(&g_cnt[b]);
        out[(size_t)b * (2 * DD) + d]      = o2f(mo);
        out[(size_t)b * (2 * DD) + DD + d] = fsum / fcnt;
        __stcg(&g_sum[b * DD + d], 0.f);
        __stcg(&g_maxo[b * DD + d], 0u);
        if (tid == 0) {
            __stcg(&g_cnt[b], 0.f);
            __stcg(&g_arrived[b], 0);
        }
    }
}

extern "C" void kernel_launch(void* const* d_in, const int* in_sizes, int n_in,
                              void* d_out, int out_size) {
    const float* feats = (const float*)d_in[0];
    const float* mask  = (const float*)d_in[1];
    float* out = (float*)d_out;

    dim3 grid(NSPLIT, BB);
    pool_strided<<<grid, 256>>>(feats, mask, out);
}